// round 16
// baseline (speedup 1.0000x reference)
#include <cuda_runtime.h>
#include <cuda.h>
#include <cuda_bf16.h>
#include <cstdint>

// ---------------------------------------------------------------------------
// BasicTransformerBlock (SD-style): self-attn + cross-attn + GEGLU.
// Dense GEMMs + self-attention on tensor cores (tf32 mma.sync, fp32 accum).
// ALL tile loads via TMA (UTMALDG) + mbarrier double buffering.
// NOTE: tcgen05 is NOT available through this toolchain (ptxas targets sm_103
// without the 'a' suffix) — legacy HMMA path is the tensor ceiling here.
// This round: flash kernel at 2 CTAs/SM (launch_bounds(256,2); smem 101.4KB*2
// fits 228KB) to hide barrier/softmax bubbles. B=2,S=4096,T=77,DIM=512,H=8,D=64.
// ---------------------------------------------------------------------------

#define BATCH 2
#define SEQ   4096
#define CTXT  77
#define DIM   512
#define NH    8
#define HD    64
#define ROWS  (BATCH * SEQ)      // 8192
#define CROWS (BATCH * CTXT)     // 154

// -------------------------- scratch (static, no allocs) --------------------
__device__ float g_xn[ROWS * DIM];
__device__ float g_q [ROWS * DIM];
__device__ float g_k [ROWS * DIM];
__device__ float g_v [ROWS * DIM];
__device__ float g_at[ROWS * DIM];
__device__ float g_h [ROWS * DIM];
__device__ float g_gg[(size_t)ROWS * 4096];
__device__ float g_ff[(size_t)ROWS * 2048];

#define MMA_TF32(acc, a0, a1, a2, a3, b0, b1)                                  \
    asm volatile(                                                              \
        "mma.sync.aligned.m16n8k8.row.col.f32.tf32.tf32.f32 "                  \
        "{%0,%1,%2,%3}, {%4,%5,%6,%7}, {%8,%9}, {%0,%1,%2,%3};\n"              \
        : "+f"(acc[0]), "+f"(acc[1]), "+f"(acc[2]), "+f"(acc[3])               \
        : "r"(a0), "r"(a1), "r"(a2), "r"(a3), "r"(b0), "r"(b1))

__device__ __forceinline__ uint32_t smem_u32(const void* p) {
    return (uint32_t)__cvta_generic_to_shared(p);
}

#define MBARRIER_INIT(addr, count)                                             \
    asm volatile("mbarrier.init.shared.b64 [%0], %1;"                          \
                 :: "r"(addr), "r"(count) : "memory")
#define MBARRIER_EXPECT_TX(addr, bytes)                                        \
    asm volatile("mbarrier.arrive.expect_tx.shared.b64 _, [%0], %1;"           \
                 :: "r"(addr), "r"(bytes) : "memory")

__device__ __forceinline__ void mbar_wait(uint32_t mbar, uint32_t phase) {
    asm volatile(
        "{\n\t.reg .pred P;\n\t"
        "WAIT_%=:\n\t"
        "mbarrier.try_wait.parity.acquire.cta.shared::cta.b64 P, [%0], %1, 0x989680;\n\t"
        "@!P bra WAIT_%=;\n\t}"
        :: "r"(mbar), "r"(phase) : "memory");
}

#define TMA2D(dst, map, x, y, mb)                                              \
    asm volatile(                                                              \
        "cp.async.bulk.tensor.2d.shared::cta.global.tile.mbarrier::complete_tx::bytes " \
        "[%0], [%1, {%2, %3}], [%4];"                                          \
        :: "r"(dst), "l"(map), "r"(x), "r"(y), "r"(mb) : "memory")

// ------------------------------ LayerNorm ----------------------------------
__global__ void ln_kernel(const float* __restrict__ in,
                          const float* __restrict__ gw,
                          const float* __restrict__ bw,
                          float* __restrict__ out) {
    const int row = blockIdx.x;
    const float* x = in + (size_t)row * DIM;
    const int t = threadIdx.x;

    float v0 = x[t];
    float v1 = x[t + 256];
    float s  = v0 + v1;
    float sq = v0 * v0 + v1 * v1;

    #pragma unroll
    for (int off = 16; off; off >>= 1) {
        s  += __shfl_xor_sync(0xffffffffu, s,  off);
        sq += __shfl_xor_sync(0xffffffffu, sq, off);
    }
    __shared__ float ss[8], sqs[8];
    if ((t & 31) == 0) { ss[t >> 5] = s; sqs[t >> 5] = sq; }
    __syncthreads();
    float S = 0.f, SQ = 0.f;
    #pragma unroll
    for (int w = 0; w < 8; w++) { S += ss[w]; SQ += sqs[w]; }

    const float mean = S * (1.0f / DIM);
    const float var  = SQ * (1.0f / DIM) - mean * mean;
    const float inv  = rsqrtf(var + 1e-5f);

    float* o = out + (size_t)row * DIM;
    o[t]       = (v0 - mean) * inv * gw[t]       + bw[t];
    o[t + 256] = (v1 - mean) * inv * gw[t + 256] + bw[t + 256];
}

// ---------------------- TF32 tensor-core GEMM (TMA) ------------------------
// 128x128x32 tile, 8 warps (2x4), warp tile 64x32, m16n8k8 tf32.
// A tile: one TMA box (32k x 128m), SW128. B tile: 4 TMA boxes (32n x 32k).
// smem per CTA: 2 stages x (16KB A + 16KB B) + 2 mbarriers + 1KB align pad.

// A frag: bank = (8ks|tg) ^ 4g -> conflict-free.
#define LOAD_AFR(dst, mf_, ks_) {                                              \
    const uint8_t* ap_ = asP + (wr * 64 + (mf_) * 16 + g) * 128;               \
    const int kb_ = ((ks_) * 8 + tg) * 4;                                      \
    const int gx_ = g << 4;                                                    \
    (dst)[0] = *(const uint32_t*)(ap_ + (kb_ ^ gx_));                          \
    (dst)[1] = *(const uint32_t*)(ap_ + 1024 + (kb_ ^ gx_));                   \
    (dst)[2] = *(const uint32_t*)(ap_ + ((kb_ + 16) ^ gx_));                   \
    (dst)[3] = *(const uint32_t*)(ap_ + 1024 + ((kb_ + 16) ^ gx_)); }
// B frag: 2-way conflict (inherent to SW128), negligible.
#define LOAD_BFR(dst, ks_) {                                                   \
    const uint8_t* b0_ = bsP + ((ks_) * 8 + tg) * 128;                         \
    const int tx0_ = tg << 4, tx1_ = (tg + 4) << 4;                            \
    _Pragma("unroll")                                                          \
    for (int nf_ = 0; nf_ < 4; nf_++) {                                        \
        const int nb_ = (nf_ * 8 + g) * 4;                                     \
        (dst)[2 * nf_]     = *(const uint32_t*)(b0_ + (nb_ ^ tx0_));           \
        (dst)[2 * nf_ + 1] = *(const uint32_t*)(b0_ + 512 + (nb_ ^ tx1_)); } }

template <bool HAS_BIAS, bool HAS_RES>
__device__ __forceinline__ void
tgemm_body(uint8_t* smraw, const CUtensorMap* mapA, const CUtensorMap* mapB,
           const float* __restrict__ bias, const float* __restrict__ Res,
           float* __restrict__ C, int M, int N, int K,
           int rowBase, int colBase) {
    const int tid  = threadIdx.x;
    const int lane = tid & 31;
    const int wid  = tid >> 5;
    const int wr   = wid >> 2;
    const int wc   = wid & 3;
    const int g    = lane >> 2;
    const int tg   = lane & 3;

    const uint32_t raw  = smem_u32(smraw);
    const uint32_t base = (raw + 1023) & ~1023u;
    uint8_t* bp = smraw + (base - raw);
    const uint32_t mbar = base + 65536;

    if (tid == 0) {
        MBARRIER_INIT(mbar, 1);
        MBARRIER_INIT(mbar + 8, 1);
    }
    __syncthreads();

    const int T = K >> 5;

    if (tid == 0) {
        #pragma unroll
        for (int s = 0; s < 2; s++) {
            const uint32_t mb = mbar + s * 8;
            MBARRIER_EXPECT_TX(mb, 32768);
            const int k0 = s << 5;
            TMA2D(base + s * 16384, mapA, k0, rowBase, mb);
            #pragma unroll
            for (int c = 0; c < 4; c++)
                TMA2D(base + 32768 + s * 16384 + c * 4096, mapB,
                      colBase + 32 * c, k0, mb);
        }
    }

    float acc[4][4][4];
    #pragma unroll
    for (int mf = 0; mf < 4; mf++)
        #pragma unroll
        for (int nf = 0; nf < 4; nf++)
            #pragma unroll
            for (int c = 0; c < 4; c++) acc[mf][nf][c] = 0.f;

    for (int t = 0; t < T; t++) {
        mbar_wait(mbar + (t & 1) * 8, (t >> 1) & 1);

        const uint8_t* asP = bp + (t & 1) * 16384;
        const uint8_t* bsP = bp + 32768 + (t & 1) * 16384 + wc * 4096;

        uint32_t afr[2][4], bfr[2][8];
        LOAD_BFR(bfr[0], 0);
        LOAD_AFR(afr[0], 0, 0);

        #pragma unroll
        for (int ks = 0; ks < 4; ks++) {
            const int kb = ks & 1;
            #pragma unroll
            for (int mf = 0; mf < 4; mf++) {
                const int cur = (ks * 4 + mf) & 1;
                const int nxt = cur ^ 1;
                if (mf < 3) {
                    LOAD_AFR(afr[nxt], mf + 1, ks);
                } else if (ks < 3) {
                    LOAD_AFR(afr[nxt], 0, ks + 1);
                    LOAD_BFR(bfr[kb ^ 1], ks + 1);
                }
                #pragma unroll
                for (int nf = 0; nf < 4; nf++)
                    MMA_TF32(acc[mf][nf],
                             afr[cur][0], afr[cur][1], afr[cur][2], afr[cur][3],
                             bfr[kb][2 * nf], bfr[kb][2 * nf + 1]);
            }
        }

        __syncthreads();   // all warps done with stage (t&1)
        if (t + 2 < T && tid == 0) {
            const int s = t & 1;
            const uint32_t mb = mbar + s * 8;
            MBARRIER_EXPECT_TX(mb, 32768);
            const int k0 = (t + 2) << 5;
            TMA2D(base + s * 16384, mapA, k0, rowBase, mb);
            #pragma unroll
            for (int c = 0; c < 4; c++)
                TMA2D(base + 32768 + s * 16384 + c * 4096, mapB,
                      colBase + 32 * c, k0, mb);
        }
    }

    #pragma unroll
    for (int mf = 0; mf < 4; mf++) {
        #pragma unroll
        for (int half = 0; half < 2; half++) {
            const int row = rowBase + wr * 64 + mf * 16 + g + 8 * half;
            if (row >= M) continue;
            #pragma unroll
            for (int nf = 0; nf < 4; nf++) {
                const int col = colBase + wc * 32 + nf * 8 + 2 * tg;
                float2 v = half ? make_float2(acc[mf][nf][2], acc[mf][nf][3])
                                : make_float2(acc[mf][nf][0], acc[mf][nf][1]);
                if (HAS_BIAS) {
                    const float2 bv = *(const float2*)&bias[col];
                    v.x += bv.x; v.y += bv.y;
                }
                if (HAS_RES) {
                    const float2 rv = *(const float2*)&Res[(size_t)row * N + col];
                    v.x += rv.x; v.y += rv.y;
                }
                *(float2*)&C[(size_t)row * N + col] = v;
            }
        }
    }
}

#define TG_SMEM (65536 + 16 + 1024)

template <bool HAS_BIAS, bool HAS_RES>
__global__ void __launch_bounds__(256, 2)
tgemm_kernel(const __grid_constant__ CUtensorMap mA,
             const __grid_constant__ CUtensorMap mB,
             const float* __restrict__ bias, const float* __restrict__ Res,
             float* __restrict__ C, int M, int N, int K) {
    __shared__ uint8_t smraw[TG_SMEM];
    tgemm_body<HAS_BIAS, HAS_RES>(smraw, &mA, &mB, bias, Res, C, M, N, K,
                                  blockIdx.y * 128, blockIdx.x * 128);
}

// Fused QKV: one launch, blockIdx.z selects weight/output (shared A).
__global__ void __launch_bounds__(256, 2)
tgemm_qkv_kernel(const __grid_constant__ CUtensorMap mA,
                 const __grid_constant__ CUtensorMap mB0,
                 const __grid_constant__ CUtensorMap mB1,
                 const __grid_constant__ CUtensorMap mB2,
                 float* __restrict__ C0, float* __restrict__ C1,
                 float* __restrict__ C2, int M, int N, int K) {
    __shared__ uint8_t smraw[TG_SMEM];
    const int z = blockIdx.z;
    const CUtensorMap* mB = (z == 0) ? &mB0 : (z == 1) ? &mB1 : &mB2;
    float* C = (z == 0) ? C0 : (z == 1) ? C1 : C2;
    tgemm_body<false, false>(smraw, &mA, mB, nullptr, nullptr, C, M, N, K,
                             blockIdx.y * 128, blockIdx.x * 128);
}

// Fused stage-2 projections: z=0 -> Q2 (M=ROWS), z=1/2 -> K2/V2 (M=CROWS).
__global__ void __launch_bounds__(256, 2)
tgemm_s2_kernel(const __grid_constant__ CUtensorMap mAxn,
                const __grid_constant__ CUtensorMap mActx,
                const __grid_constant__ CUtensorMap mBq,
                const __grid_constant__ CUtensorMap mBk,
                const __grid_constant__ CUtensorMap mBv,
                float* __restrict__ Cq, float* __restrict__ Ck,
                float* __restrict__ Cv) {
    __shared__ uint8_t smraw[TG_SMEM];
    const int z = blockIdx.z;
    if (z > 0 && (int)blockIdx.y * 128 >= CROWS) return;
    const CUtensorMap* mA = (z == 0) ? &mAxn : &mActx;
    const CUtensorMap* mB = (z == 0) ? &mBq : (z == 1) ? &mBk : &mBv;
    float* C = (z == 0) ? Cq : (z == 1) ? Ck : Cv;
    const int M = (z == 0) ? ROWS : CROWS;
    tgemm_body<false, false>(smraw, mA, mB, nullptr, nullptr, C, M, DIM, DIM,
                             blockIdx.y * 128, blockIdx.x * 128);
}

// ---------------- Flash self-attention on tensor cores (tf32) --------------
// grid (SEQ/128, B*H), 256 threads = 8 warps; warp owns 16 q-rows x 64 keys.
// K/V tiles via TMA (2 SW128 boxes of 32d x 64keys each), double-buffered.
// 2 CTAs/SM (smem 101.4KB x2 = 202.8KB <= 228KB; regs capped at 128).
#define FS 68
#define KFRAG(dst, ks_, nf_) {                                                 \
    const uint8_t* p_ = ksP + (((ks_) >= 4) ? 8192 : 0) + ((nf_) * 8 + g) * 128; \
    const int d4_ = (((ks_) & 3) * 8 + tg) * 4;                                \
    const int gx_ = g << 4;                                                    \
    (dst)[0] = *(const uint32_t*)(p_ + (d4_ ^ gx_));                           \
    (dst)[1] = *(const uint32_t*)(p_ + ((d4_ + 16) ^ gx_)); }
#define VFRAG(dst, ks_, nf_) {                                                 \
    const uint8_t* p_ = vsP + (((nf_) >= 4) ? 8192 : 0) + ((ks_) * 8 + tg) * 128; \
    const int d4_ = (((nf_) & 3) * 8 + g) * 4;                                 \
    (dst)[0] = *(const uint32_t*)(p_ + (d4_ ^ (tg << 4)));                     \
    (dst)[1] = *(const uint32_t*)(p_ + 512 + (d4_ ^ ((tg + 4) << 4))); }

__global__ void __launch_bounds__(256, 2)
flash_mma_kernel(const __grid_constant__ CUtensorMap mK,
                 const __grid_constant__ CUtensorMap mV,
                 const float* __restrict__ Q, float* __restrict__ O) {
    extern __shared__ uint8_t fsm[];
    const uint32_t raw  = smem_u32(fsm);
    const uint32_t base = (raw + 1023) & ~1023u;
    uint8_t* bp = fsm + (base - raw);
    uint32_t* QP = (uint32_t*)(bp + 65536);       // [128][FS]
    const uint32_t mbar = base + 65536 + 34816;

    const int bh = blockIdx.y;
    const int b = bh >> 3, h = bh & 7;
    const int q0 = blockIdx.x * 128;
    const int tid = threadIdx.x;
    const int lane = tid & 31;
    const int wid = tid >> 5;
    const int g = lane >> 2, tg = lane & 3;

    if (tid == 0) {
        MBARRIER_INIT(mbar, 1);
        MBARRIER_INIT(mbar + 8, 1);
    }
    __syncthreads();

    // ---- prologue: TMA for tiles 0,1 ----
    if (tid == 0) {
        #pragma unroll
        for (int s = 0; s < 2; s++) {
            const uint32_t mb = mbar + s * 8;
            MBARRIER_EXPECT_TX(mb, 32768);
            const int y = b * SEQ + s * 64;
            #pragma unroll
            for (int c = 0; c < 2; c++) {
                TMA2D(base + s * 16384 + c * 8192,         &mK, h * HD + 32 * c, y, mb);
                TMA2D(base + 32768 + s * 16384 + c * 8192, &mV, h * HD + 32 * c, y, mb);
            }
        }
    }

    // ---- stage Q tile to smem (scale folded; raw fp32 bits) ----
    {
        const int li = tid >> 1;             // 0..127 (warp-private band)
        const int db = (tid & 1) * 32;
        const float* qrow = &Q[((size_t)(b * SEQ + q0 + li)) * DIM + h * HD];
        #pragma unroll
        for (int c = 0; c < 8; c++) {
            const int d4 = db + 4 * c;
            const float4 qv = *(const float4*)&qrow[d4];
            uint4 u = make_uint4(__float_as_uint(qv.x * 0.125f),
                                 __float_as_uint(qv.y * 0.125f),
                                 __float_as_uint(qv.z * 0.125f),
                                 __float_as_uint(qv.w * 0.125f));
            *(uint4*)&QP[li * FS + d4] = u;
        }
    }
    __syncwarp();

    const int r0 = wid * 16 + g;
    uint32_t qf[8][4];
    #pragma unroll
    for (int ks = 0; ks < 8; ks++) {
        qf[ks][0] = QP[r0 * FS + ks * 8 + tg];
        qf[ks][1] = QP[(r0 + 8) * FS + ks * 8 + tg];
        qf[ks][2] = QP[r0 * FS + ks * 8 + tg + 4];
        qf[ks][3] = QP[(r0 + 8) * FS + ks * 8 + tg + 4];
    }

    float m0 = -1e30f, m1 = -1e30f, l0 = 0.f, l1 = 0.f;
    float oacc[8][4];
    #pragma unroll
    for (int nf = 0; nf < 8; nf++)
        #pragma unroll
        for (int c = 0; c < 4; c++) oacc[nf][c] = 0.f;

    const int T = SEQ / 64;
    for (int t = 0; t < T; t++) {
        mbar_wait(mbar + (t & 1) * 8, (t >> 1) & 1);

        const uint8_t* ksP = bp + (t & 1) * 16384;
        const uint8_t* vsP = bp + 32768 + (t & 1) * 16384;

        // ---- GEMM1: S[16x64] = Qw @ K^T (frag prefetch pipeline) ----
        float sacc[8][4];
        #pragma unroll
        for (int nf = 0; nf < 8; nf++)
            #pragma unroll
            for (int c = 0; c < 4; c++) sacc[nf][c] = 0.f;

        {
            uint32_t kf[2][2];
            KFRAG(kf[0], 0, 0);
            #pragma unroll
            for (int ks = 0; ks < 8; ks++) {
                #pragma unroll
                for (int nf = 0; nf < 8; nf++) {
                    const int cur = (ks * 8 + nf) & 1;
                    if (!(ks == 7 && nf == 7)) {
                        const int nn = (nf < 7) ? nf + 1 : 0;
                        const int kk = (nf < 7) ? ks : ks + 1;
                        KFRAG(kf[cur ^ 1], kk, nn);
                    }
                    MMA_TF32(sacc[nf], qf[ks][0], qf[ks][1], qf[ks][2], qf[ks][3],
                             kf[cur][0], kf[cur][1]);
                }
            }
        }

        // ---- online softmax ----
        float mx0 = -1e30f, mx1 = -1e30f;
        #pragma unroll
        for (int nf = 0; nf < 8; nf++) {
            mx0 = fmaxf(mx0, fmaxf(sacc[nf][0], sacc[nf][1]));
            mx1 = fmaxf(mx1, fmaxf(sacc[nf][2], sacc[nf][3]));
        }
        mx0 = fmaxf(mx0, __shfl_xor_sync(0xffffffffu, mx0, 1));
        mx0 = fmaxf(mx0, __shfl_xor_sync(0xffffffffu, mx0, 2));
        mx1 = fmaxf(mx1, __shfl_xor_sync(0xffffffffu, mx1, 1));
        mx1 = fmaxf(mx1, __shfl_xor_sync(0xffffffffu, mx1, 2));

        const float mn0 = fmaxf(m0, mx0);
        const float mn1 = fmaxf(m1, mx1);
        const float al0 = __expf(m0 - mn0);
        const float al1 = __expf(m1 - mn1);

        float rs0 = 0.f, rs1 = 0.f;
        #pragma unroll
        for (int nf = 0; nf < 8; nf++) {
            const float p00 = __expf(sacc[nf][0] - mn0);
            const float p01 = __expf(sacc[nf][1] - mn0);
            const float p10 = __expf(sacc[nf][2] - mn1);
            const float p11 = __expf(sacc[nf][3] - mn1);
            rs0 += p00 + p01;
            rs1 += p10 + p11;
            *(uint2*)&QP[r0 * FS + nf * 8 + 2 * tg] =
                make_uint2(__float_as_uint(p00), __float_as_uint(p01));
            *(uint2*)&QP[(r0 + 8) * FS + nf * 8 + 2 * tg] =
                make_uint2(__float_as_uint(p10), __float_as_uint(p11));
            oacc[nf][0] *= al0; oacc[nf][1] *= al0;
            oacc[nf][2] *= al1; oacc[nf][3] *= al1;
        }
        rs0 += __shfl_xor_sync(0xffffffffu, rs0, 1);
        rs0 += __shfl_xor_sync(0xffffffffu, rs0, 2);
        rs1 += __shfl_xor_sync(0xffffffffu, rs1, 1);
        rs1 += __shfl_xor_sync(0xffffffffu, rs1, 2);
        l0 = l0 * al0 + rs0;
        l1 = l1 * al1 + rs1;
        m0 = mn0; m1 = mn1;
        __syncwarp();   // P band is warp-private

        // ---- GEMM2: O += P @ V (frag prefetch pipeline) ----
        {
            uint32_t vf[2][2];
            VFRAG(vf[0], 0, 0);
            #pragma unroll
            for (int ks = 0; ks < 8; ks++) {
                const uint32_t a0 = QP[r0 * FS + ks * 8 + tg];
                const uint32_t a1 = QP[(r0 + 8) * FS + ks * 8 + tg];
                const uint32_t a2 = QP[r0 * FS + ks * 8 + tg + 4];
                const uint32_t a3 = QP[(r0 + 8) * FS + ks * 8 + tg + 4];
                #pragma unroll
                for (int nf = 0; nf < 8; nf++) {
                    const int cur = (ks * 8 + nf) & 1;
                    if (!(ks == 7 && nf == 7)) {
                        const int nn = (nf < 7) ? nf + 1 : 0;
                        const int kk = (nf < 7) ? ks : ks + 1;
                        VFRAG(vf[cur ^ 1], kk, nn);
                    }
                    MMA_TF32(oacc[nf], a0, a1, a2, a3, vf[cur][0], vf[cur][1]);
                }
            }
        }

        __syncthreads();   // all warps done with stage (t&1)
        if (t + 2 < T && tid == 0) {
            const int s = t & 1;
            const uint32_t mb = mbar + s * 8;
            MBARRIER_EXPECT_TX(mb, 32768);
            const int y = b * SEQ + (t + 2) * 64;
            #pragma unroll
            for (int c = 0; c < 2; c++) {
                TMA2D(base + s * 16384 + c * 8192,         &mK, h * HD + 32 * c, y, mb);
                TMA2D(base + 32768 + s * 16384 + c * 8192, &mV, h * HD + 32 * c, y, mb);
            }
        }
    }

    const float inv0 = 1.0f / l0;
    const float inv1 = 1.0f / l1;
    const size_t base0 = ((size_t)(b * SEQ + q0 + r0)) * DIM + h * HD;
    const size_t base1 = ((size_t)(b * SEQ + q0 + r0 + 8)) * DIM + h * HD;
    #pragma unroll
    for (int nf = 0; nf < 8; nf++) {
        const int col = nf * 8 + 2 * tg;
        *(float2*)&O[base0 + col] = make_float2(oacc[nf][0] * inv0, oacc[nf][1] * inv0);
        *(float2*)&O[base1 + col] = make_float2(oacc[nf][2] * inv1, oacc[nf][3] * inv1);
    }
}

// --------------------------- Cross attention (T=77) ------------------------
__global__ void __launch_bounds__(256)
cross_attn_kernel(const float* __restrict__ Q, const float* __restrict__ K,
                  const float* __restrict__ V, float* __restrict__ O) {
    __shared__ float Ksm[CTXT][65];
    __shared__ float Vsm[CTXT][65];

    const int bh = blockIdx.y;
    const int b = bh >> 3, h = bh & 7;
    const int warp = threadIdx.x >> 5, lane = threadIdx.x & 31;

    for (int idx = threadIdx.x; idx < CTXT * HD; idx += 256) {
        const int j = idx >> 6, d = idx & 63;
        const size_t base = ((size_t)(b * CTXT + j)) * DIM + h * HD + d;
        Ksm[j][d] = K[base];
        Vsm[j][d] = V[base];
    }
    __syncthreads();

    const float scale = 0.125f;
    const int q_base = blockIdx.x * 64 + warp * 8;

    for (int qq = 0; qq < 8; qq++) {
        const int qi = q_base + qq;
        const float* qp = &Q[((size_t)(b * SEQ + qi)) * DIM + h * HD];
        const float q0v = qp[lane];
        const float q1v = qp[lane + 32];

        const int j0 = lane, j1 = lane + 32, j2 = lane + 64;
        float s0 = 0.f, s1 = 0.f, s2 = 0.f;
        #pragma unroll
        for (int d = 0; d < 32; d++) {
            const float qd = __shfl_sync(0xffffffffu, q0v, d);
            s0 = fmaf(qd, Ksm[j0][d], s0);
            s1 = fmaf(qd, Ksm[j1][d], s1);
            if (j2 < CTXT) s2 = fmaf(qd, Ksm[j2][d], s2);
        }
        #pragma unroll
        for (int d = 0; d < 32; d++) {
            const float qd = __shfl_sync(0xffffffffu, q1v, d);
            s0 = fmaf(qd, Ksm[j0][d + 32], s0);
            s1 = fmaf(qd, Ksm[j1][d + 32], s1);
            if (j2 < CTXT) s2 = fmaf(qd, Ksm[j2][d + 32], s2);
        }
        s0 *= scale; s1 *= scale;
        s2 = (j2 < CTXT) ? s2 * scale : -1e30f;

        float mx = fmaxf(fmaxf(s0, s1), s2);
        #pragma unroll
        for (int off = 16; off; off >>= 1)
            mx = fmaxf(mx, __shfl_xor_sync(0xffffffffu, mx, off));

        const float p0 = __expf(s0 - mx);
        const float p1 = __expf(s1 - mx);
        const float p2 = (j2 < CTXT) ? __expf(s2 - mx) : 0.f;
        float sum = p0 + p1 + p2;
        #pragma unroll
        for (int off = 16; off; off >>= 1)
            sum += __shfl_xor_sync(0xffffffffu, sum, off);

        float o0 = 0.f, o1 = 0.f;
        #pragma unroll
        for (int ll = 0; ll < 32; ll++) {
            const float pj = __shfl_sync(0xffffffffu, p0, ll);
            o0 = fmaf(pj, Vsm[ll][lane],      o0);
            o1 = fmaf(pj, Vsm[ll][lane + 32], o1);
        }
        #pragma unroll
        for (int ll = 0; ll < 32; ll++) {
            const float pj = __shfl_sync(0xffffffffu, p1, ll);
            o0 = fmaf(pj, Vsm[32 + ll][lane],      o0);
            o1 = fmaf(pj, Vsm[32 + ll][lane + 32], o1);
        }
        #pragma unroll
        for (int ll = 0; ll < 13; ll++) {
            const float pj = __shfl_sync(0xffffffffu, p2, ll);
            o0 = fmaf(pj, Vsm[64 + ll][lane],      o0);
            o1 = fmaf(pj, Vsm[64 + ll][lane + 32], o1);
        }

        const float inv = 1.0f / sum;
        float* op = &O[((size_t)(b * SEQ + qi)) * DIM + h * HD];
        op[lane]      = o0 * inv;
        op[lane + 32] = o1 * inv;
    }
}

// ------------------------------ GEGLU --------------------------------------
__global__ void geglu_kernel(const float* __restrict__ gg, float* __restrict__ ff) {
    const size_t idx = (size_t)blockIdx.x * 256 + threadIdx.x;
    const size_t mrow = idx >> 11;
    const int    n    = (int)(idx & 2047);
    const float y    = gg[mrow * 4096 + n];
    const float gate = gg[mrow * 4096 + 2048 + n];
    const float t = tanhf(gate * 0.7978845608f * (1.0f + 0.044715f * gate * gate));
    ff[idx] = y * 0.5f * gate * (1.0f + t);
}

// ------------------------------ host helpers --------------------------------
typedef CUresult (*TmEncodeFn)(CUtensorMap*, CUtensorMapDataType, cuuint32_t,
                               void*, const cuuint64_t*, const cuuint64_t*,
                               const cuuint32_t*, const cuuint32_t*,
                               CUtensorMapInterleave, CUtensorMapSwizzle,
                               CUtensorMapL2promotion, CUtensorMapFloatOOBfill);

static void build_map(TmEncodeFn enc, CUtensorMap* m, const void* ptr,
                      unsigned long long d0, unsigned long long d1,
                      unsigned b0, unsigned b1) {
    cuuint64_t dims[2]    = {d0, d1};
    cuuint64_t strides[1] = {d0 * 4};
    cuuint32_t box[2]     = {b0, b1};
    cuuint32_t es[2]      = {1, 1};
    enc(m, CU_TENSOR_MAP_DATA_TYPE_FLOAT32, 2, const_cast<void*>(ptr),
        dims, strides, box, es, CU_TENSOR_MAP_INTERLEAVE_NONE,
        CU_TENSOR_MAP_SWIZZLE_128B, CU_TENSOR_MAP_L2_PROMOTION_L2_128B,
        CU_TENSOR_MAP_FLOAT_OOB_FILL_NONE);
}

// ------------------------------ launch -------------------------------------
extern "C" void kernel_launch(void* const* d_in, const int* in_sizes, int n_in,
                              void* d_out, int out_size) {
    (void)in_sizes; (void)n_in; (void)out_size;
    const float* x       = (const float*)d_in[0];
    const float* context = (const float*)d_in[1];
    const float* ln1_g   = (const float*)d_in[2];
    const float* ln1_b   = (const float*)d_in[3];
    const float* wq1     = (const float*)d_in[4];
    const float* wk1     = (const float*)d_in[5];
    const float* wv1     = (const float*)d_in[6];
    const float* wo1     = (const float*)d_in[7];
    const float* bo1     = (const float*)d_in[8];
    const float* ln2_g   = (const float*)d_in[9];
    const float* ln2_b   = (const float*)d_in[10];
    const float* wq2     = (const float*)d_in[11];
    const float* wk2     = (const float*)d_in[12];
    const float* wv2     = (const float*)d_in[13];
    const float* wo2     = (const float*)d_in[14];
    const float* bo2     = (const float*)d_in[15];
    const float* ln3_g   = (const float*)d_in[16];
    const float* ln3_b   = (const float*)d_in[17];
    const float* geglu_w = (const float*)d_in[18];
    const float* geglu_b = (const float*)d_in[19];
    const float* out_w   = (const float*)d_in[20];
    const float* out_b   = (const float*)d_in[21];
    float* out = (float*)d_out;

    float *xn, *q, *k, *v, *at, *h, *gg, *ff;
    cudaGetSymbolAddress((void**)&xn, g_xn);
    cudaGetSymbolAddress((void**)&q,  g_q);
    cudaGetSymbolAddress((void**)&k,  g_k);
    cudaGetSymbolAddress((void**)&v,  g_v);
    cudaGetSymbolAddress((void**)&at, g_at);
    cudaGetSymbolAddress((void**)&h,  g_h);
    cudaGetSymbolAddress((void**)&gg, g_gg);
    cudaGetSymbolAddress((void**)&ff, g_ff);

    // tensormap encode via driver entry point (no libcuda link needed)
    void* encp = nullptr;
    cudaDriverEntryPointQueryResult qres;
    cudaGetDriverEntryPoint("cuTensorMapEncodeTiled", &encp,
                            cudaEnableDefault, &qres);
    TmEncodeFn enc = (TmEncodeFn)encp;

    // A maps: dims (K, M), box (32, 128)
    CUtensorMap mXn, mAt, mCtx, mFf;
    build_map(enc, &mXn,  xn,      512,  ROWS,  32, 128);
    build_map(enc, &mAt,  at,      512,  ROWS,  32, 128);
    build_map(enc, &mCtx, context, 512,  CROWS, 32, 128);
    build_map(enc, &mFf,  ff,      2048, ROWS,  32, 128);
    // B maps: dims (N, K), box (32, 32)
    CUtensorMap mWq1, mWk1, mWv1, mWo1, mWq2, mWk2, mWv2, mWo2, mWgg, mWout;
    build_map(enc, &mWq1, wq1,     512,  512,  32, 32);
    build_map(enc, &mWk1, wk1,     512,  512,  32, 32);
    build_map(enc, &mWv1, wv1,     512,  512,  32, 32);
    build_map(enc, &mWo1, wo1,     512,  512,  32, 32);
    build_map(enc, &mWq2, wq2,     512,  512,  32, 32);
    build_map(enc, &mWk2, wk2,     512,  512,  32, 32);
    build_map(enc, &mWv2, wv2,     512,  512,  32, 32);
    build_map(enc, &mWo2, wo2,     512,  512,  32, 32);
    build_map(enc, &mWgg, geglu_w, 4096, 512,  32, 32);
    build_map(enc, &mWout, out_w,  512,  2048, 32, 32);
    // flash K/V maps: dims (DIM, ROWS), box (32, 64)
    CUtensorMap mKt, mVt;
    build_map(enc, &mKt, k, 512, ROWS, 32, 64);
    build_map(enc, &mVt, v, 512, ROWS, 32, 64);

    // flash dyn smem: Ks 32KB + Vs 32KB + QP 34816 + mbar 16 + pad 1024
    const size_t fa_smem = 65536 + 34816 + 16 + 1024;
    cudaFuncSetAttribute(flash_mma_kernel,
                         cudaFuncAttributeMaxDynamicSharedMemorySize, (int)fa_smem);

    const dim3 blk(256);
    const dim3 gqkv(DIM / 128, ROWS / 128, 3);       // (4, 64, 3)
    const dim3 g512(DIM / 128, ROWS / 128);          // (4, 64)
    const dim3 g4096(4096 / 128, ROWS / 128);        // (32, 64)
    const dim3 gattn(SEQ / 128, BATCH * NH);         // (32, 16)
    const dim3 gxattn(SEQ / 64, BATCH * NH);         // (64, 16)

    // ---- stage 1: self-attention ----
    ln_kernel<<<ROWS, blk>>>(x, ln1_g, ln1_b, xn);
    tgemm_qkv_kernel<<<gqkv, blk>>>(mXn, mWq1, mWk1, mWv1, q, k, v, ROWS, DIM, DIM);
    flash_mma_kernel<<<gattn, blk, fa_smem>>>(mKt, mVt, q, at);
    tgemm_kernel<true, true><<<g512, blk>>>(mAt, mWo1, bo1, x, h, ROWS, DIM, DIM);

    // ---- stage 2: cross-attention ----
    ln_kernel<<<ROWS, blk>>>(h, ln2_g, ln2_b, xn);
    tgemm_s2_kernel<<<gqkv, blk>>>(mXn, mCtx, mWq2, mWk2, mWv2, q, k, v);
    cross_attn_kernel<<<gxattn, blk>>>(q, k, v, at);
    tgemm_kernel<true, true><<<g512, blk>>>(mAt, mWo2, bo2, h, h, ROWS, DIM, DIM);

    // ---- stage 3: GEGLU FFN ----
    ln_kernel<<<ROWS, blk>>>(h, ln3_g, ln3_b, xn);
    tgemm_kernel<true, false><<<g4096, blk>>>(mXn, mWgg, geglu_b, nullptr, gg, ROWS, 4096, DIM);
    geglu_kernel<<<(ROWS * 2048) / 256, blk>>>(gg, ff);
    tgemm_kernel<true, true><<<g512, blk>>>(mFf, mWout, out_b, h, out, ROWS, DIM, 2048);
}